// round 4
// baseline (speedup 1.0000x reference)
#include <cuda_runtime.h>
#include <cstdint>

// AggregateLevels: FPN anchor generation + delta decode, 5 levels fused.
// B=16, IH=IW=1024. Levels i=2..6: h=w = 256,128,64,32,16.
// Total anchor positions A = 261888. Each thread handles 4 consecutive
// positions (same level/aspect/row guaranteed: all boundaries are multiples
// of 4 and rem%4==0, w%4==0) -> all memory ops are 128-bit.
// Output (float32): scores [B,A,2] @0 ; boxes [B,A,4] @B*A*2 ; anchors [B,A,4] @B*A*6.

#define B_SZ   16
#define A_TOT  261888
#define TPB    192          // A_TOT/4 = 65472 = 341 * 192

__constant__ int   c_off[5]   = {0, 196608, 245760, 258048, 261120};
__constant__ int   c_lghw[5]  = {16, 14, 12, 10, 8};
__constant__ int   c_lgw[5]   = {8, 7, 6, 5, 4};
__constant__ float c_scale[5] = {4.f, 8.f, 16.f, 32.f, 64.f};
__constant__ float c_half[5]  = {1.5f, 3.5f, 7.5f, 15.5f, 31.5f};
__constant__ float c_anch[5]  = {0.0625f, 0.125f, 0.25f, 0.5f, 1.0f}; // 2^(i-6)

struct Ptrs {
    const float* cs[5];
    const float* bp[5];
    const int*   ih;
    const int*   iw;
};

__global__ __launch_bounds__(TPB)
void aggregate_levels_kernel(Ptrs ptrs, float* __restrict__ out) {
    const int t = blockIdx.x * TPB + threadIdx.x;   // < A_TOT/4
    const int p = t << 2;                           // base anchor position
    const int b = blockIdx.y;

    // level decode: 4 compares
    const int l = (p >= 196608) + (p >= 245760) + (p >= 258048) + (p >= 261120);

    const int q     = p - c_off[l];
    const int lghw  = c_lghw[l];
    const int hw    = 1 << lghw;
    const int hw4   = hw >> 2;            // in float4 units
    const int a     = q >> lghw;          // aspect 0..2
    const int rem   = q & (hw - 1);       // y*w + x, multiple of 4
    const int lgw   = c_lgw[l];
    const int y     = rem >> lgw;
    const int x     = rem & ((1 << lgw) - 1);

    // 6 independent 128-bit loads (MLP=6, 96B in flight per thread)
    const float4* cs = reinterpret_cast<const float4*>(
        ptrs.cs[l] + (((b * 6 + a * 2) << lghw) + rem));
    const float4 c0 = __ldg(cs);
    const float4 c1 = __ldg(cs + hw4);

    const float4* bp = reinterpret_cast<const float4*>(
        ptrs.bp[l] + (((b * 12 + a * 4) << lghw) + rem));
    const float4 d0 = __ldg(bp);
    const float4 d1 = __ldg(bp + hw4);
    const float4 d2 = __ldg(bp + 2 * hw4);
    const float4 d3 = __ldg(bp + 3 * hw4);

    const float fih = (float)(*ptrs.ih);
    const float fiw = (float)(*ptrs.iw);

    const float s    = c_scale[l];
    const float half = c_half[l];
    const float a_cy = s * (float)y + half;
    const float ha   = fih * c_anch[l];
    const float wa   = fiw * c_anch[l];
    const float a_h  = (a == 2) ? 2.0f * ha : ha;   // hs = {ha, ha, 2ha}
    const float a_w  = (a == 0) ? 2.0f * wa : wa;   // ws = {2wa, wa, wa}

    const float D0[4] = {d0.x, d0.y, d0.z, d0.w};
    const float D1[4] = {d1.x, d1.y, d1.z, d1.w};
    const float D2[4] = {d2.x, d2.y, d2.z, d2.w};
    const float D3[4] = {d3.x, d3.y, d3.z, d3.w};

    float4 box[4], anc[4];
    #pragma unroll
    for (int j = 0; j < 4; ++j) {
        const float a_cx = s * (float)(x + j) + half;
        const float cyc  = a_cy + D0[j] * a_h;
        const float cxc  = a_cx + D1[j] * a_w;
        const float hh   = a_h * __expf(D2[j]);
        const float ww   = a_w * __expf(D3[j]);
        const float y1 = fminf(fmaxf(cyc - 0.5f * hh, 0.0f), fih);
        const float x1 = fminf(fmaxf(cxc - 0.5f * ww, 0.0f), fiw);
        const float y2 = fminf(fmaxf(cyc + 0.5f * hh, 0.0f), fih);
        const float x2 = fminf(fmaxf(cxc + 0.5f * ww, 0.0f), fiw);
        box[j] = make_float4(y1, x1, y2, x2);
        anc[j] = make_float4(a_cy, a_cx, a_h, a_w);
    }

    const size_t idx = (size_t)b * A_TOT + p;       // multiple of 4

    // scores: 4 positions x (c0,c1) = 32B -> two STG.128
    float4* os = reinterpret_cast<float4*>(out);    // scores region viewed as float4
    const size_t sidx = idx >> 1;                   // (idx*2 floats)/4
    os[sidx]     = make_float4(c0.x, c1.x, c0.y, c1.y);
    os[sidx + 1] = make_float4(c0.z, c1.z, c0.w, c1.w);

    float4* ob = reinterpret_cast<float4*>(out + (size_t)B_SZ * A_TOT * 2);
    float4* oa = reinterpret_cast<float4*>(out + (size_t)B_SZ * A_TOT * 6);
    #pragma unroll
    for (int j = 0; j < 4; ++j) {
        ob[idx + j] = box[j];
        oa[idx + j] = anc[j];
    }
}

extern "C" void kernel_launch(void* const* d_in, const int* in_sizes, int n_in,
                              void* d_out, int out_size) {
    (void)out_size;
    // Identify inputs by element count (robust to metadata ordering).
    // Level l=0..4 (FPN i=l+2): hw = 65536>>(2*l); cs has 16*6*hw elems,
    // bp has 16*12*hw elems; all counts distinct. Scalars have size 1
    // (dict order: img_h then img_w).
    Ptrs ptrs;
    ptrs.ih = nullptr; ptrs.iw = nullptr;
    for (int i = 0; i < n_in; ++i) {
        const long long sz = in_sizes[i];
        if (sz == 1) {
            if (!ptrs.ih) ptrs.ih = (const int*)d_in[i];
            else          ptrs.iw = (const int*)d_in[i];
            continue;
        }
        for (int l = 0; l < 5; ++l) {
            const long long hw = 65536LL >> (2 * l);
            if (sz == 16LL * 6 * hw)  ptrs.cs[l] = (const float*)d_in[i];
            if (sz == 16LL * 12 * hw) ptrs.bp[l] = (const float*)d_in[i];
        }
    }

    dim3 grid((A_TOT / 4) / TPB, B_SZ);   // 341 x 16
    aggregate_levels_kernel<<<grid, TPB>>>(ptrs, (float*)d_out);
}

// round 7
// speedup vs baseline: 1.7689x; 1.7689x over previous
#include <cuda_runtime.h>
#include <cstdint>

// AggregateLevels: FPN anchor generation + delta decode, 5 levels fused.
// B=16, IH=IW=1024. Levels i=2..6: h=w = 256,128,64,32,16. A = 261888.
// One position per thread-iteration (keeps ALL loads and stores perfectly
// warp-contiguous), 2 independent iterations per thread for MLP.
// Output (float32): scores [B,A,2] @0 ; boxes [B,A,4] @B*A*2 ; anchors [B,A,4] @B*A*6.

#define B_SZ   16
#define A_TOT  261888
#define TPB    256
#define GRIDX  512          // ceil(A_TOT / (TPB*2)); only p1 of last block OOB

__constant__ int   c_off[5]   = {0, 196608, 245760, 258048, 261120};
__constant__ int   c_lghw[5]  = {16, 14, 12, 10, 8};
__constant__ int   c_lgw[5]   = {8, 7, 6, 5, 4};
__constant__ float c_scale[5] = {4.f, 8.f, 16.f, 32.f, 64.f};
__constant__ float c_half[5]  = {1.5f, 3.5f, 7.5f, 15.5f, 31.5f};
__constant__ float c_anch[5]  = {0.0625f, 0.125f, 0.25f, 0.5f, 1.0f}; // 2^(i-6)

struct Ptrs {
    const float* cs[5];
    const float* bp[5];
    const int*   ih;
    const int*   iw;
};

__global__ __launch_bounds__(TPB)
void aggregate_levels_kernel(Ptrs ptrs, float* __restrict__ out) {
    const int b  = blockIdx.y;
    const int p0 = blockIdx.x * (TPB * 2) + threadIdx.x;

    int   p[2];  p[0] = p0;  p[1] = p0 + TPB;
    bool  ok[2]; ok[0] = true; ok[1] = (p[1] < A_TOT);   // p0 always < A_TOT for GRIDX=512

    const float fih = (float)(*ptrs.ih);
    const float fiw = (float)(*ptrs.iw);

    // ---- address phase: issue all 12 loads before any compute ----
    int   l[2], a[2], yy[2], xx[2];
    float sc[2], hf[2], an[2];
    float c0[2], c1[2], d0[2], d1[2], d2[2], d3[2];

    #pragma unroll
    for (int k = 0; k < 2; ++k) {
        const int pp = ok[k] ? p[k] : 0;
        const int lv = (pp >= 196608) + (pp >= 245760) + (pp >= 258048) + (pp >= 261120);
        l[k] = lv;
        const int q    = pp - c_off[lv];
        const int lghw = c_lghw[lv];
        const int hw   = 1 << lghw;
        a[k]           = q >> lghw;
        const int rem  = q & (hw - 1);
        const int lgw  = c_lgw[lv];
        yy[k] = rem >> lgw;
        xx[k] = rem & ((1 << lgw) - 1);
        sc[k] = c_scale[lv];
        hf[k] = c_half[lv];
        an[k] = c_anch[lv];

        const float* cs = ptrs.cs[lv] + (((b * 6 + a[k] * 2) << lghw) + rem);
        const float* bp = ptrs.bp[lv] + (((b * 12 + a[k] * 4) << lghw) + rem);
        c0[k] = __ldcs(cs);
        c1[k] = __ldcs(cs + hw);
        d0[k] = __ldcs(bp);
        d1[k] = __ldcs(bp + hw);
        d2[k] = __ldcs(bp + 2 * hw);
        d3[k] = __ldcs(bp + 3 * hw);
    }

    // ---- compute + store phase ----
    float2* os = reinterpret_cast<float2*>(out);
    float4* ob = reinterpret_cast<float4*>(out + (size_t)B_SZ * A_TOT * 2);
    float4* oa = reinterpret_cast<float4*>(out + (size_t)B_SZ * A_TOT * 6);

    #pragma unroll
    for (int k = 0; k < 2; ++k) {
        if (!ok[k]) continue;
        const float a_cy = sc[k] * (float)yy[k] + hf[k];
        const float a_cx = sc[k] * (float)xx[k] + hf[k];
        const float ha   = fih * an[k];
        const float wa   = fiw * an[k];
        const float a_h  = (a[k] == 2) ? 2.0f * ha : ha;   // hs = {ha, ha, 2ha}
        const float a_w  = (a[k] == 0) ? 2.0f * wa : wa;   // ws = {2wa, wa, wa}

        const float cyc = a_cy + d0[k] * a_h;
        const float cxc = a_cx + d1[k] * a_w;
        const float hh  = a_h * __expf(d2[k]);
        const float ww  = a_w * __expf(d3[k]);

        const float y1 = fminf(fmaxf(cyc - 0.5f * hh, 0.0f), fih);
        const float x1 = fminf(fmaxf(cxc - 0.5f * ww, 0.0f), fiw);
        const float y2 = fminf(fmaxf(cyc + 0.5f * hh, 0.0f), fih);
        const float x2 = fminf(fmaxf(cxc + 0.5f * ww, 0.0f), fiw);

        const size_t idx = (size_t)b * A_TOT + p[k];
        __stcs(os + idx, make_float2(c0[k], c1[k]));
        __stcs(ob + idx, make_float4(y1, x1, y2, x2));
        __stcs(oa + idx, make_float4(a_cy, a_cx, a_h, a_w));
    }
}

extern "C" void kernel_launch(void* const* d_in, const int* in_sizes, int n_in,
                              void* d_out, int out_size) {
    (void)out_size;
    // Identify inputs by element count (robust to metadata ordering).
    // Level l=0..4 (FPN i=l+2): hw = 65536>>(2*l); cs has 16*6*hw elems,
    // bp has 16*12*hw elems; all counts distinct. Scalars have size 1
    // (dict order: img_h then img_w).
    Ptrs ptrs;
    ptrs.ih = nullptr; ptrs.iw = nullptr;
    for (int i = 0; i < n_in; ++i) {
        const long long sz = in_sizes[i];
        if (sz == 1) {
            if (!ptrs.ih) ptrs.ih = (const int*)d_in[i];
            else          ptrs.iw = (const int*)d_in[i];
            continue;
        }
        for (int l = 0; l < 5; ++l) {
            const long long hw = 65536LL >> (2 * l);
            if (sz == 16LL * 6 * hw)  ptrs.cs[l] = (const float*)d_in[i];
            if (sz == 16LL * 12 * hw) ptrs.bp[l] = (const float*)d_in[i];
        }
    }

    dim3 grid(GRIDX, B_SZ);
    aggregate_levels_kernel<<<grid, TPB>>>(ptrs, (float*)d_out);
}

// round 8
// speedup vs baseline: 1.9872x; 1.1234x over previous
#include <cuda_runtime.h>
#include <cstdint>

// AggregateLevels: FPN anchor generation + delta decode, 5 levels fused.
// B=16, IH=IW=1024. Levels i=2..6: h=w = 256,128,64,32,16. A = 261888.
// One position per thread-iteration (ALL loads and stores warp-contiguous),
// 4 independent iterations per thread (p, p+256, p+512, p+768) for MLP.
// Output (float32): scores [B,A,2] @0 ; boxes [B,A,4] @B*A*2 ; anchors [B,A,4] @B*A*6.

#define B_SZ   16
#define A_TOT  261888
#define TPB    256
#define ILP    4
#define GRIDX  256          // ceil(A_TOT / (TPB*ILP)) = ceil(261888/1024) = 256

__constant__ int   c_off[5]   = {0, 196608, 245760, 258048, 261120};
__constant__ int   c_lghw[5]  = {16, 14, 12, 10, 8};
__constant__ int   c_lgw[5]   = {8, 7, 6, 5, 4};
__constant__ float c_scale[5] = {4.f, 8.f, 16.f, 32.f, 64.f};
__constant__ float c_half[5]  = {1.5f, 3.5f, 7.5f, 15.5f, 31.5f};
__constant__ float c_anch[5]  = {0.0625f, 0.125f, 0.25f, 0.5f, 1.0f}; // 2^(i-6)

struct Ptrs {
    const float* cs[5];
    const float* bp[5];
    const int*   ih;
    const int*   iw;
};

__global__ __launch_bounds__(TPB)
void aggregate_levels_kernel(Ptrs ptrs, float* __restrict__ out) {
    const int b  = blockIdx.y;
    const int p0 = blockIdx.x * (TPB * ILP) + threadIdx.x;

    const float fih = (float)(*ptrs.ih);
    const float fiw = (float)(*ptrs.iw);

    // ---- address + load phase: issue all 24 loads before any compute ----
    int   p[ILP], aa[ILP], yy[ILP], xx[ILP];
    bool  ok[ILP];
    float sc[ILP], hf[ILP], an[ILP];
    float c0[ILP], c1[ILP], d0[ILP], d1[ILP], d2[ILP], d3[ILP];

    #pragma unroll
    for (int k = 0; k < ILP; ++k) {
        p[k]  = p0 + k * TPB;
        ok[k] = (p[k] < A_TOT);
        const int pp = ok[k] ? p[k] : 0;
        const int lv = (pp >= 196608) + (pp >= 245760) + (pp >= 258048) + (pp >= 261120);
        const int q    = pp - c_off[lv];
        const int lghw = c_lghw[lv];
        const int hw   = 1 << lghw;
        aa[k]          = q >> lghw;           // aspect 0..2
        const int rem  = q & (hw - 1);
        const int lgw  = c_lgw[lv];
        yy[k] = rem >> lgw;
        xx[k] = rem & ((1 << lgw) - 1);
        sc[k] = c_scale[lv];
        hf[k] = c_half[lv];
        an[k] = c_anch[lv];

        const float* cs = ptrs.cs[lv] + (((b * 6  + aa[k] * 2) << lghw) + rem);
        const float* bp = ptrs.bp[lv] + (((b * 12 + aa[k] * 4) << lghw) + rem);
        c0[k] = __ldcs(cs);
        c1[k] = __ldcs(cs + hw);
        d0[k] = __ldcs(bp);
        d1[k] = __ldcs(bp + hw);
        d2[k] = __ldcs(bp + 2 * hw);
        d3[k] = __ldcs(bp + 3 * hw);
    }

    // ---- compute + store phase ----
    float2* os = reinterpret_cast<float2*>(out);
    float4* ob = reinterpret_cast<float4*>(out + (size_t)B_SZ * A_TOT * 2);
    float4* oa = reinterpret_cast<float4*>(out + (size_t)B_SZ * A_TOT * 6);

    #pragma unroll
    for (int k = 0; k < ILP; ++k) {
        if (!ok[k]) continue;
        const float a_cy = sc[k] * (float)yy[k] + hf[k];
        const float a_cx = sc[k] * (float)xx[k] + hf[k];
        const float ha   = fih * an[k];
        const float wa   = fiw * an[k];
        const float a_h  = (aa[k] == 2) ? 2.0f * ha : ha;   // hs = {ha, ha, 2ha}
        const float a_w  = (aa[k] == 0) ? 2.0f * wa : wa;   // ws = {2wa, wa, wa}

        const float cyc = a_cy + d0[k] * a_h;
        const float cxc = a_cx + d1[k] * a_w;
        const float hh  = a_h * __expf(d2[k]);
        const float ww  = a_w * __expf(d3[k]);

        const float y1 = fminf(fmaxf(cyc - 0.5f * hh, 0.0f), fih);
        const float x1 = fminf(fmaxf(cxc - 0.5f * ww, 0.0f), fiw);
        const float y2 = fminf(fmaxf(cyc + 0.5f * hh, 0.0f), fih);
        const float x2 = fminf(fmaxf(cxc + 0.5f * ww, 0.0f), fiw);

        const size_t idx = (size_t)b * A_TOT + p[k];
        __stcs(os + idx, make_float2(c0[k], c1[k]));
        __stcs(ob + idx, make_float4(y1, x1, y2, x2));
        __stcs(oa + idx, make_float4(a_cy, a_cx, a_h, a_w));
    }
}

extern "C" void kernel_launch(void* const* d_in, const int* in_sizes, int n_in,
                              void* d_out, int out_size) {
    (void)out_size;
    // Identify inputs by element count (robust to metadata ordering).
    // Level l=0..4 (FPN i=l+2): hw = 65536>>(2*l); cs has 16*6*hw elems,
    // bp has 16*12*hw elems; all counts distinct. Scalars have size 1
    // (dict order: img_h then img_w).
    Ptrs ptrs;
    ptrs.ih = nullptr; ptrs.iw = nullptr;
    for (int i = 0; i < n_in; ++i) {
        const long long sz = in_sizes[i];
        if (sz == 1) {
            if (!ptrs.ih) ptrs.ih = (const int*)d_in[i];
            else          ptrs.iw = (const int*)d_in[i];
            continue;
        }
        for (int l = 0; l < 5; ++l) {
            const long long hw = 65536LL >> (2 * l);
            if (sz == 16LL * 6 * hw)  ptrs.cs[l] = (const float*)d_in[i];
            if (sz == 16LL * 12 * hw) ptrs.bp[l] = (const float*)d_in[i];
        }
    }

    dim3 grid(GRIDX, B_SZ);
    aggregate_levels_kernel<<<grid, TPB>>>(ptrs, (float*)d_out);
}